// round 14
// baseline (speedup 1.0000x reference)
#include <cuda_runtime.h>
#include <cuda_fp16.h>
#include <cstdint>

#define NUM_B 16
#define SEQ_N 1025
#define NHEAD 12
#define HDIM  64
#define DMODEL 768
#define M_ROWS 16400
#define NBH (NUM_B * NHEAD)       // 192

// ---- packed geometry (fp16) ----
#define KG 48                     // 768/16
#define KGP 24                    // 768/32 (kg-pairs)
#define A_MG 1025                 // 16400/16
#define APK_SZ (A_MG * KG * 128)
#define WQ_NG 288                 // 2304/8
#define WP_NG 96
#define QBUF_BH (65 * 4 * 128)    // 33280 u32 per bh
#define KVBUF_BH (17 * 2048)      // 34816 u32 per bh
#define LOG2E 1.44269504088896340736f

// ---------------- scratch (fp16 bit patterns, packed) ----------------
__device__ uint32_t g_xt[APK_SZ];
__device__ uint32_t g_ctxp[APK_SZ];
__device__ uint32_t g_wq[WQ_NG * KGP * 128];
__device__ uint32_t g_wp[WP_NG * KGP * 128];
__device__ uint32_t g_Q[NBH * QBUF_BH];
__device__ uint32_t g_K[NBH * KVBUF_BH];
__device__ uint32_t g_V[NBH * KVBUF_BH];

__device__ __forceinline__ uint32_t f2h2(float lo, float hi) {
    __half2 h = __floats2half2_rn(lo, hi);
    return *(uint32_t*)&h;
}
__device__ __forceinline__ uint32_t p_exp2(float lo, float hi) {
    uint32_t r;
    asm("{\n\t.reg .b32 t;\n\t"
        "cvt.rn.f16x2.f32 t, %2, %1;\n\t"
        "ex2.approx.f16x2 %0, t;\n\t}"
        : "=r"(r) : "f"(lo), "f"(hi));
    return r;
}
__device__ __forceinline__ void mma16(float* c, const uint32_t* a, uint32_t b0, uint32_t b1) {
    asm volatile(
        "mma.sync.aligned.m16n8k16.row.col.f32.f16.f16.f32 "
        "{%0,%1,%2,%3}, {%4,%5,%6,%7}, {%8,%9}, {%0,%1,%2,%3};\n"
        : "+f"(c[0]), "+f"(c[1]), "+f"(c[2]), "+f"(c[3])
        : "r"(a[0]), "r"(a[1]), "r"(a[2]), "r"(a[3]), "r"(b0), "r"(b1));
}
__device__ __forceinline__ void cpa16(uint32_t dst, const void* src, int sz) {
    asm volatile("cp.async.cg.shared.global [%0], [%1], 16, %2;\n"
                 :: "r"(dst), "l"(src), "r"(sz));
}
__device__ __forceinline__ void cpa16u(uint32_t dst, const void* src) {
    asm volatile("cp.async.cg.shared.global [%0], [%1], 16;\n"
                 :: "r"(dst), "l"(src));
}
#define CPA_COMMIT() asm volatile("cp.async.commit_group;\n")
#define CPA_WAIT0()  asm volatile("cp.async.wait_group 0;\n")
#define CPA_WAIT1()  asm volatile("cp.async.wait_group 1;\n")

// ---------------- prepass (identical to R13) ----------------
__global__ void pack_a(const float* __restrict__ src, uint32_t* __restrict__ dst, int n)
{
    int id = blockIdx.x * 256 + threadIdx.x;
    if (id >= n) return;
    int m = id / 384;
    int c = id - m * 384;
    float2 v = *(const float2*)&src[(size_t)m * DMODEL + c * 2];
    dst[((size_t)(m >> 4) * KG + (c >> 3)) * 128
        + ((m & 7) * 4 + (c & 3)) * 4 + ((m >> 3) & 1) + 2 * ((c >> 2) & 1)]
        = f2h2(v.x, v.y);
}
__global__ void pack_w(const float* __restrict__ src, uint32_t* __restrict__ dst, int n)
{
    int id = blockIdx.x * 256 + threadIdx.x;
    if (id >= n) return;
    int nn = id / 384;
    int c = id - nn * 384;
    float2 v = *(const float2*)&src[(size_t)nn * DMODEL + c * 2];
    dst[((size_t)(nn >> 3) * KGP + (c >> 4)) * 128
        + ((nn & 7) * 4 + (c & 3)) * 4 + ((c >> 3) & 1) * 2 + ((c >> 2) & 1)]
        = f2h2(v.x, v.y);
}
__global__ void zero_pad()
{
    int id = blockIdx.x * 256 + threadIdx.x;
    if (id >= NBH * 2048) return;
    int bh = id >> 11;
    int i = id & 2047;
    g_K[(size_t)bh * KVBUF_BH + 16 * 2048 + i] = 0;
    g_V[(size_t)bh * KVBUF_BH + 16 * 2048 + i] = 0;
}

// =================================================================
// TN GEMM, fp16 TC, 3-stage cp.async, k-step 64 (2 kg-pairs/stage).
// Stage: A 4096 u32 | B 4096 u32 = 32KB; 3 stages = 96KB.
// =================================================================
#define GEMM_SMEM_BYTES (3 * 8192 * 4)

template<int MODE>
__global__ __launch_bounds__(256, 2) void gemm_tc(
    float* __restrict__ out, const float* __restrict__ bias,
    const float* __restrict__ freqs)
{
    extern __shared__ uint32_t gsm[];

    const int tid = threadIdx.x;
    const int lane = tid & 31;
    const int wid = tid >> 5;
    const int wm = wid & 3;
    const int wn = wid >> 2;
    const int m0 = blockIdx.x * 128;
    const int n0 = blockIdx.y * 128;

    const uint32_t* Ag = (MODE == 1) ? g_ctxp : g_xt;
    const uint32_t* Bg = (MODE == 1) ? g_wp : g_wq;

    const uint32_t smAddr = (uint32_t)__cvta_generic_to_shared(gsm);

    float c[2][8][4];
#pragma unroll
    for (int i = 0; i < 2; i++)
#pragma unroll
        for (int j = 0; j < 8; j++)
#pragma unroll
            for (int r = 0; r < 4; r++) c[i][j][r] = 0.f;

    const int s7 = lane >> 2;
    const int l3 = lane & 3;
    const int mg0 = m0 >> 4;
    const int ng0 = n0 >> 3;

    // stage s at gsm + s*8192: A blocks [mb(8)*4+kgi(4)] x 128, then B [nb(16)*2+kp(2)] x 128
    auto stage_ld = [&](int k0, int s) {
        const int kg0 = k0 >> 4;
        const int kp0 = k0 >> 5;
        // A: 1024 chunks (32 blocks x 128 u32)
#pragma unroll
        for (int it = 0; it < 4; it++) {
            int ch = tid + it * 256;
            int blk = ch >> 5;                 // mb = blk>>2, kgi = blk&3
            int inner = (ch & 31) * 4;
            int mg = mg0 + (blk >> 2);
            int sz = (mg < A_MG) ? 16 : 0;
            cpa16(smAddr + (s * 8192 + blk * 128 + inner) * 4,
                  &Ag[((size_t)mg * KG + kg0 + (blk & 3)) * 128 + inner], sz);
        }
        // B: 1024 chunks (32 blocks x 128 u32)
#pragma unroll
        for (int it = 0; it < 4; it++) {
            int ch = tid + it * 256;
            int blk = ch >> 5;                 // nb = blk>>1, kp = blk&1
            int inner = (ch & 31) * 4;
            cpa16u(smAddr + (s * 8192 + 4096 + blk * 128 + inner) * 4,
                   &Bg[((size_t)(ng0 + (blk >> 1)) * KGP + kp0 + (blk & 1)) * 128 + inner]);
        }
        CPA_COMMIT();
    };

    stage_ld(0, 0);
    stage_ld(64, 1);

    for (int k0 = 0, it = 0; k0 < DMODEL; k0 += 64, it++) {
        if (k0 + 64 < DMODEL) CPA_WAIT1(); else CPA_WAIT0();
        __syncthreads();
        if (k0 + 128 < DMODEL) stage_ld(k0 + 128, (it + 2) % 3);

        const uint32_t* Ab = gsm + (it % 3) * 8192;
        const uint32_t* Bb = Ab + 4096;

#pragma unroll
        for (int kp = 0; kp < 2; kp++) {
            uint4 bv[8];
#pragma unroll
            for (int nt = 0; nt < 8; nt++)
                bv[nt] = *(const uint4*)&Bb[(((wn * 8 + nt) * 2 + kp) << 7) + lane * 4];
#pragma unroll
            for (int kgi = 0; kgi < 2; kgi++) {
                uint32_t a[2][4];
#pragma unroll
                for (int mt = 0; mt < 2; mt++) {
                    uint4 av = *(const uint4*)&Ab[(((wm * 2 + mt) * 4 + kp * 2 + kgi) << 7) + lane * 4];
                    a[mt][0] = av.x; a[mt][1] = av.y; a[mt][2] = av.z; a[mt][3] = av.w;
                }
#pragma unroll
                for (int mt = 0; mt < 2; mt++)
#pragma unroll
                    for (int nt = 0; nt < 8; nt++) {
                        if (kgi == 0) mma16(c[mt][nt], a[mt], bv[nt].x, bv[nt].y);
                        else          mma16(c[mt][nt], a[mt], bv[nt].z, bv[nt].w);
                    }
            }
        }
    }

    // -------- epilogue (identical to R13) --------
    if (MODE == 0) {
        const int sidx = n0 / DMODEL;
        const int hh = ((n0 % DMODEL) >> 6) + wn;
        const float qscale = 0.125f * LOG2E;
#pragma unroll
        for (int nt = 0; nt < 8; nt++) {
            int e0 = nt * 8 + 2 * l3;
            float f0 = 0.f, f1 = 0.f;
            if (sidx < 2) {
                int fi = hh * 32 + (e0 >> 1);
                f0 = freqs[fi];
                f1 = freqs[384 + fi];
            }
#pragma unroll
            for (int mt = 0; mt < 2; mt++)
#pragma unroll
                for (int hr = 0; hr < 2; hr++) {
                    int row = m0 + wm * 32 + mt * 16 + s7 + hr * 8;
                    if (row >= M_ROWS) continue;
                    int bb = row / SEQ_N;
                    int n = row - bb * SEQ_N;
                    float v0 = c[mt][nt][hr * 2 + 0];
                    float v1 = c[mt][nt][hr * 2 + 1];
                    if (sidx < 2 && n >= 1) {
                        int t = n - 1;
                        float ang = (float)(t & 31) * f0 + (float)(t >> 5) * f1;
                        float sn, cs;
                        sincosf(ang, &sn, &cs);
                        float a0 = v0, b0 = v1;
                        v0 = a0 * cs - b0 * sn;
                        v1 = a0 * sn + b0 * cs;
                    }
                    int bh = bb * NHEAD + hh;
                    if (sidx == 0) {
                        size_t pos = (size_t)bh * QBUF_BH
                            + (size_t)((n >> 4) * 4 + (e0 >> 4)) * 128
                            + ((n & 7) * 4 + l3) * 4 + ((n >> 3) & 1) + 2 * (nt & 1);
                        g_Q[pos] = f2h2(v0 * qscale, v1 * qscale);
                    } else if (sidx == 1) {
                        size_t pos = (size_t)bh * KVBUF_BH + (size_t)(n >> 6) * 2048
                            + (size_t)(((n & 63) >> 3) * 2 + (nt >> 2)) * 128
                            + ((n & 7) * 4 + l3) * 4 + ((nt >> 1) & 1) * 2 + (nt & 1);
                        g_K[pos] = f2h2(v0, v1);
                    } else {
                        size_t p0 = (size_t)bh * KVBUF_BH + (size_t)(n >> 6) * 2048
                            + (size_t)((e0 >> 3) * 2 + ((n >> 5) & 1)) * 128
                            + ((e0 & 7) * 4 + ((n & 7) >> 1)) * 4
                            + (((n >> 4) & 1) * 2) + ((n >> 3) & 1);
                        __half* hp = (__half*)g_V;
                        hp[p0 * 2 + (n & 1)] = __float2half(v0);
                        hp[(p0 + 16) * 2 + (n & 1)] = __float2half(v1);
                    }
                }
        }
    } else {
#pragma unroll
        for (int nt = 0; nt < 8; nt++) {
            int col = n0 + wn * 64 + nt * 8 + 2 * l3;
            float b0v = bias[col], b1v = bias[col + 1];
#pragma unroll
            for (int mt = 0; mt < 2; mt++)
#pragma unroll
                for (int hr = 0; hr < 2; hr++) {
                    int row = m0 + wm * 32 + mt * 16 + s7 + hr * 8;
                    if (row >= M_ROWS) continue;
                    *(float2*)&out[(size_t)row * DMODEL + col] =
                        make_float2(c[mt][nt][hr * 2 + 0] + b0v,
                                    c[mt][nt][hr * 2 + 1] + b1v);
                }
        }
    }
}

// =================================================================
// Flash attention, fp16 TC, max-free exp2 softmax, paired K/V
// LDS.128 layouts, 2 KV tiles per pipeline stage (9 syncs, not 17).
// 3 stages x 32KB = 96KB. 256 threads, 128 q/block.
// =================================================================
#define ATTN_SMEM_BYTES (3 * 8192 * 4)

__global__ __launch_bounds__(256, 2) void attn_tc()
{
    extern __shared__ uint32_t dsm[];

    const int tid = threadIdx.x;
    const int lane = tid & 31;
    const int w = tid >> 5;
    const int bx = blockIdx.x;
    const int q0 = bx * 128;
    const int bh = blockIdx.y;

    const uint32_t* Kg = g_K + (size_t)bh * KVBUF_BH;
    const uint32_t* Vg = g_V + (size_t)bh * KVBUF_BH;
    const uint32_t smBase = (uint32_t)__cvta_generic_to_shared(dsm);

    // stage s: [tile0 K 2048 | tile0 V 2048 | tile1 K 2048 | tile1 V 2048]
    auto issue_kv2 = [&](int si, int s) {
        const uint32_t buf = smBase + s * 8192 * 4;
#pragma unroll
        for (int t = 0; t < 2; t++) {
            int kt = si * 2 + t;
            if (kt < 17) {
                const uint32_t* ks = Kg + kt * 2048;
                const uint32_t* vs = Vg + kt * 2048;
#pragma unroll
                for (int it = 0; it < 2; it++) {
                    int ch = tid + it * 256;
                    cpa16u(buf + t * 16384 + ch * 16, ks + ch * 4);
                    cpa16u(buf + t * 16384 + 8192 + ch * 16, vs + ch * 4);
                }
            }
        }
        CPA_COMMIT();
    };

    const int qg = bx * 8 + w;
    const bool act = (qg < 65);
    uint32_t qa[4][4];
    if (act) {
        const uint32_t* Qg = g_Q + (size_t)bh * QBUF_BH + (size_t)qg * 512;
#pragma unroll
        for (int kg = 0; kg < 4; kg++) {
            uint4 qv = *(const uint4*)&Qg[kg * 128 + lane * 4];
            qa[kg][0] = qv.x; qa[kg][1] = qv.y; qa[kg][2] = qv.z; qa[kg][3] = qv.w;
        }
    }

    float of[8][4];
#pragma unroll
    for (int i = 0; i < 8; i++)
#pragma unroll
        for (int j = 0; j < 4; j++) of[i][j] = 0.f;
    float lc[4] = {0.f, 0.f, 0.f, 0.f};

    issue_kv2(0, 0);
    issue_kv2(1, 1);

    for (int si = 0; si < 9; si++) {
        if (si + 1 < 9) CPA_WAIT1(); else CPA_WAIT0();
        __syncthreads();
        if (si + 2 < 9) issue_kv2(si + 2, (si + 2) % 3);

        if (act) {
#pragma unroll
            for (int t = 0; t < 2; t++) {
                const int kt = si * 2 + t;
                if (kt >= 17) break;
                const int kv0 = kt * 64;
                const uint32_t* Ks = dsm + (si % 3) * 8192 + t * 4096;
                const uint32_t* Vs = Ks + 2048;

                // ---- S = Q K^T ----
                float s[8][4];
#pragma unroll
                for (int i = 0; i < 8; i++)
#pragma unroll
                    for (int j = 0; j < 4; j++) s[i][j] = 0.f;
#pragma unroll
                for (int nt = 0; nt < 8; nt++) {
                    uint4 u = *(const uint4*)&Ks[nt * 256 + lane * 4];
                    uint4 v = *(const uint4*)&Ks[nt * 256 + 128 + lane * 4];
                    mma16(s[nt], qa[0], u.x, u.y);
                    mma16(s[nt], qa[1], u.z, u.w);
                    mma16(s[nt], qa[2], v.x, v.y);
                    mma16(s[nt], qa[3], v.z, v.w);
                }

                if (kt == 16) {
#pragma unroll
                    for (int nt = 0; nt < 8; nt++) {
                        int col = kv0 + nt * 8 + 2 * (lane & 3);
                        if (col >= SEQ_N)     { s[nt][0] = -1e30f; s[nt][2] = -1e30f; }
                        if (col + 1 >= SEQ_N) { s[nt][1] = -1e30f; s[nt][3] = -1e30f; }
                    }
                }

                // ---- P = exp2(S) in fp16 A-frag form ----
                uint32_t pa[4][4];
#pragma unroll
                for (int kg = 0; kg < 4; kg++) {
                    pa[kg][0] = p_exp2(s[2 * kg][0],     s[2 * kg][1]);
                    pa[kg][1] = p_exp2(s[2 * kg][2],     s[2 * kg][3]);
                    pa[kg][2] = p_exp2(s[2 * kg + 1][0], s[2 * kg + 1][1]);
                    pa[kg][3] = p_exp2(s[2 * kg + 1][2], s[2 * kg + 1][3]);
                }

                // ---- l += P @ ones ----
#pragma unroll
                for (int kg = 0; kg < 4; kg++)
                    mma16(lc, pa[kg], 0x3C003C00u, 0x3C003C00u);

                // ---- O += P V ----
#pragma unroll
                for (int ne = 0; ne < 8; ne++) {
                    uint4 u = *(const uint4*)&Vs[ne * 256 + lane * 4];
                    uint4 v = *(const uint4*)&Vs[ne * 256 + 128 + lane * 4];
                    mma16(of[ne], pa[0], u.x, u.y);
                    mma16(of[ne], pa[1], u.z, u.w);
                    mma16(of[ne], pa[2], v.x, v.y);
                    mma16(of[ne], pa[3], v.z, v.w);
                }
            }
        }
    }

    // ---- normalize + write ctx (packed A-frag, fp16 bits) ----
    if (act) {
        float inv0 = 1.f / lc[0], inv1 = 1.f / lc[2];
        const int hh = bh % NHEAD;
        const int bb = bh / NHEAD;
        const int l3 = lane & 3;
        const int qr0 = q0 + w * 16 + (lane >> 2);
        const int qr1 = qr0 + 8;
#pragma unroll
        for (int ne = 0; ne < 8; ne++) {
            int d = hh * 64 + ne * 8 + 2 * l3;
            int kg = d >> 4;
            if (qr0 < SEQ_N) {
                int m = bb * SEQ_N + qr0;
                size_t pos = ((size_t)(m >> 4) * KG + kg) * 128
                    + ((m & 7) * 4 + l3) * 4 + ((m >> 3) & 1) + 2 * (ne & 1);
                g_ctxp[pos] = f2h2(of[ne][0] * inv0, of[ne][1] * inv0);
            }
            if (qr1 < SEQ_N) {
                int m = bb * SEQ_N + qr1;
                size_t pos = ((size_t)(m >> 4) * KG + kg) * 128
                    + ((m & 7) * 4 + l3) * 4 + ((m >> 3) & 1) + 2 * (ne & 1);
                g_ctxp[pos] = f2h2(of[ne][2] * inv1, of[ne][3] * inv1);
            }
        }
    }
}

// =================================================================
extern "C" void kernel_launch(void* const* d_in, const int* in_sizes, int n_in,
                              void* d_out, int out_size)
{
    const float* x     = (const float*)d_in[0];
    const float* Wqkv  = (const float*)d_in[1];
    const float* Wproj = (const float*)d_in[2];
    const float* bproj = (const float*)d_in[3];
    const float* freqs = (const float*)d_in[4];
    float* out = (float*)d_out;

    uint32_t* xt;  cudaGetSymbolAddress((void**)&xt, g_xt);
    uint32_t* wq;  cudaGetSymbolAddress((void**)&wq, g_wq);
    uint32_t* wp;  cudaGetSymbolAddress((void**)&wp, g_wp);

    cudaFuncSetAttribute(gemm_tc<0>, cudaFuncAttributeMaxDynamicSharedMemorySize,
                         GEMM_SMEM_BYTES);
    cudaFuncSetAttribute(gemm_tc<1>, cudaFuncAttributeMaxDynamicSharedMemorySize,
                         GEMM_SMEM_BYTES);
    cudaFuncSetAttribute(attn_tc, cudaFuncAttributeMaxDynamicSharedMemorySize,
                         ATTN_SMEM_BYTES);

    // 0) prepass
    {
        int na = M_ROWS * 384;
        pack_a<<<(na + 255) / 256, 256>>>(x, xt, na);
        int nq = 2304 * 384;
        pack_w<<<(nq + 255) / 256, 256>>>(Wqkv, wq, nq);
        int np = 768 * 384;
        pack_w<<<(np + 255) / 256, 256>>>(Wproj, wp, np);
        zero_pad<<<(NBH * 2048 + 255) / 256, 256>>>();
    }
    // 1) QKV GEMM + fused RoPE -> packed Q/K/V
    {
        dim3 grid((M_ROWS + 127) / 128, (3 * DMODEL) / 128);
        gemm_tc<0><<<grid, 256, GEMM_SMEM_BYTES>>>(nullptr, nullptr, freqs);
    }
    // 2) attention -> packed ctx
    {
        dim3 grid((SEQ_N + 127) / 128, NBH);
        attn_tc<<<grid, 256, ATTN_SMEM_BYTES>>>();
    }
    // 3) proj GEMM + bias -> out
    {
        dim3 grid((M_ROWS + 127) / 128, DMODEL / 128);
        gemm_tc<1><<<grid, 256, GEMM_SMEM_BYTES>>>(out, bproj, nullptr);
    }
}

// round 16
// speedup vs baseline: 1.0055x; 1.0055x over previous
#include <cuda_runtime.h>
#include <cuda_fp16.h>
#include <cstdint>

#define NUM_B 16
#define SEQ_N 1025
#define NHEAD 12
#define HDIM  64
#define DMODEL 768
#define M_ROWS 16400
#define NBH (NUM_B * NHEAD)       // 192

// ---- packed geometry (fp16) ----
#define KG 48                     // 768/16
#define KGP 24                    // 768/32 (kg-pairs)
#define A_MG 1025                 // 16400/16
#define APK_SZ (A_MG * KG * 128)
#define WQ_NG 288                 // 2304/8
#define WP_NG 96
#define QBUF_BH (65 * 4 * 128)    // 33280 u32 per bh
#define KVBUF_BH (17 * 2048)      // 34816 u32 per bh
#define LOG2E 1.44269504088896340736f

// ---------------- scratch (fp16 bit patterns, packed) ----------------
__device__ uint32_t g_xt[APK_SZ];
__device__ uint32_t g_ctxp[APK_SZ];
__device__ uint32_t g_wq[WQ_NG * KGP * 128];
__device__ uint32_t g_wp[WP_NG * KGP * 128];
__device__ uint32_t g_Q[NBH * QBUF_BH];
__device__ uint32_t g_K[NBH * KVBUF_BH];
__device__ uint32_t g_V[NBH * KVBUF_BH];

__device__ __forceinline__ uint32_t f2h2(float lo, float hi) {
    __half2 h = __floats2half2_rn(lo, hi);
    return *(uint32_t*)&h;
}
__device__ __forceinline__ uint32_t p_exp2(float lo, float hi) {
    uint32_t r;
    asm("{\n\t.reg .b32 t;\n\t"
        "cvt.rn.f16x2.f32 t, %2, %1;\n\t"
        "ex2.approx.f16x2 %0, t;\n\t}"
        : "=r"(r) : "f"(lo), "f"(hi));
    return r;
}
__device__ __forceinline__ float2 h2f2(uint32_t h) {
    return __half22float2(*(__half2*)&h);
}
__device__ __forceinline__ void mma16(float* c, const uint32_t* a, uint32_t b0, uint32_t b1) {
    asm volatile(
        "mma.sync.aligned.m16n8k16.row.col.f32.f16.f16.f32 "
        "{%0,%1,%2,%3}, {%4,%5,%6,%7}, {%8,%9}, {%0,%1,%2,%3};\n"
        : "+f"(c[0]), "+f"(c[1]), "+f"(c[2]), "+f"(c[3])
        : "r"(a[0]), "r"(a[1]), "r"(a[2]), "r"(a[3]), "r"(b0), "r"(b1));
}
__device__ __forceinline__ void cpa16(uint32_t dst, const void* src, int sz) {
    asm volatile("cp.async.cg.shared.global [%0], [%1], 16, %2;\n"
                 :: "r"(dst), "l"(src), "r"(sz));
}
__device__ __forceinline__ void cpa16u(uint32_t dst, const void* src) {
    asm volatile("cp.async.cg.shared.global [%0], [%1], 16;\n"
                 :: "r"(dst), "l"(src));
}
#define CPA_COMMIT() asm volatile("cp.async.commit_group;\n")
#define CPA_WAIT0()  asm volatile("cp.async.wait_group 0;\n")
#define CPA_WAIT1()  asm volatile("cp.async.wait_group 1;\n")

// ---------------- prepass (identical to R13) ----------------
__global__ void pack_a(const float* __restrict__ src, uint32_t* __restrict__ dst, int n)
{
    int id = blockIdx.x * 256 + threadIdx.x;
    if (id >= n) return;
    int m = id / 384;
    int c = id - m * 384;
    float2 v = *(const float2*)&src[(size_t)m * DMODEL + c * 2];
    dst[((size_t)(m >> 4) * KG + (c >> 3)) * 128
        + ((m & 7) * 4 + (c & 3)) * 4 + ((m >> 3) & 1) + 2 * ((c >> 2) & 1)]
        = f2h2(v.x, v.y);
}
__global__ void pack_w(const float* __restrict__ src, uint32_t* __restrict__ dst, int n)
{
    int id = blockIdx.x * 256 + threadIdx.x;
    if (id >= n) return;
    int nn = id / 384;
    int c = id - nn * 384;
    float2 v = *(const float2*)&src[(size_t)nn * DMODEL + c * 2];
    dst[((size_t)(nn >> 3) * KGP + (c >> 4)) * 128
        + ((nn & 7) * 4 + (c & 3)) * 4 + ((c >> 3) & 1) * 2 + ((c >> 2) & 1)]
        = f2h2(v.x, v.y);
}
__global__ void zero_pad()
{
    int id = blockIdx.x * 256 + threadIdx.x;
    if (id >= NBH * 2048) return;
    int bh = id >> 11;
    int i = id & 2047;
    g_K[(size_t)bh * KVBUF_BH + 16 * 2048 + i] = 0;
    g_V[(size_t)bh * KVBUF_BH + 16 * 2048 + i] = 0;
}

// =================================================================
// TN GEMM, fp16 TC (m16n8k16), 3-stage cp.async, packed frags.
// (identical to R13 — proven)
// =================================================================
#define GEMM_SMEM_BYTES (3 * 4096 * 4)

template<int MODE>
__global__ __launch_bounds__(256, 2) void gemm_tc(
    float* __restrict__ out, const float* __restrict__ bias,
    const float* __restrict__ freqs)
{
    extern __shared__ uint32_t gsm[];

    const int tid = threadIdx.x;
    const int lane = tid & 31;
    const int wid = tid >> 5;
    const int wm = wid & 3;
    const int wn = wid >> 2;
    const int m0 = blockIdx.x * 128;
    const int n0 = blockIdx.y * 128;

    const uint32_t* Ag = (MODE == 1) ? g_ctxp : g_xt;
    const uint32_t* Bg = (MODE == 1) ? g_wp : g_wq;

    const uint32_t smAddr = (uint32_t)__cvta_generic_to_shared(gsm);

    float c[2][8][4];
#pragma unroll
    for (int i = 0; i < 2; i++)
#pragma unroll
        for (int j = 0; j < 8; j++)
#pragma unroll
            for (int r = 0; r < 4; r++) c[i][j][r] = 0.f;

    const int s7 = lane >> 2;
    const int l3 = lane & 3;
    const int mg0 = m0 >> 4;
    const int ng0 = n0 >> 3;

    auto stage_ld = [&](int k0, int s) {
        const int kg0 = k0 >> 4;
        const int kp0 = k0 >> 5;
#pragma unroll
        for (int it = 0; it < 2; it++) {
            int ch = tid + it * 256;
            int blk = ch >> 5;
            int inner = (ch & 31) * 4;
            int mg = mg0 + (blk >> 1);
            int sz = (mg < A_MG) ? 16 : 0;
            cpa16(smAddr + (s * 4096 + blk * 128 + inner) * 4,
                  &Ag[((size_t)mg * KG + kg0 + (blk & 1)) * 128 + inner], sz);
        }
#pragma unroll
        for (int it = 0; it < 2; it++) {
            int ch = tid + it * 256;
            int nb = ch >> 5;
            int inner = (ch & 31) * 4;
            cpa16u(smAddr + (s * 4096 + 2048 + nb * 128 + inner) * 4,
                   &Bg[((size_t)(ng0 + nb) * KGP + kp0) * 128 + inner]);
        }
        CPA_COMMIT();
    };

    stage_ld(0, 0);
    stage_ld(32, 1);

    for (int k0 = 0, it = 0; k0 < DMODEL; k0 += 32, it++) {
        if (k0 + 32 < DMODEL) CPA_WAIT1(); else CPA_WAIT0();
        __syncthreads();
        if (k0 + 64 < DMODEL) stage_ld(k0 + 64, (it + 2) % 3);

        const uint32_t* Ab = gsm + (it % 3) * 4096;
        const uint32_t* Bb = Ab + 2048;

        uint4 bv[8];
#pragma unroll
        for (int nt = 0; nt < 8; nt++)
            bv[nt] = *(const uint4*)&Bb[((wn * 8 + nt) << 7) + lane * 4];

#pragma unroll
        for (int kgi = 0; kgi < 2; kgi++) {
            uint32_t a[2][4];
#pragma unroll
            for (int mt = 0; mt < 2; mt++) {
                uint4 av = *(const uint4*)&Ab[(((wm * 2 + mt) * 2 + kgi) << 7) + lane * 4];
                a[mt][0] = av.x; a[mt][1] = av.y; a[mt][2] = av.z; a[mt][3] = av.w;
            }
#pragma unroll
            for (int mt = 0; mt < 2; mt++)
#pragma unroll
                for (int nt = 0; nt < 8; nt++) {
                    if (kgi == 0) mma16(c[mt][nt], a[mt], bv[nt].x, bv[nt].y);
                    else          mma16(c[mt][nt], a[mt], bv[nt].z, bv[nt].w);
                }
        }
    }

    // -------- epilogue (identical to R13) --------
    if (MODE == 0) {
        const int sidx = n0 / DMODEL;
        const int hh = ((n0 % DMODEL) >> 6) + wn;
        const float qscale = 0.125f * LOG2E;
#pragma unroll
        for (int nt = 0; nt < 8; nt++) {
            int e0 = nt * 8 + 2 * l3;
            float f0 = 0.f, f1 = 0.f;
            if (sidx < 2) {
                int fi = hh * 32 + (e0 >> 1);
                f0 = freqs[fi];
                f1 = freqs[384 + fi];
            }
#pragma unroll
            for (int mt = 0; mt < 2; mt++)
#pragma unroll
                for (int hr = 0; hr < 2; hr++) {
                    int row = m0 + wm * 32 + mt * 16 + s7 + hr * 8;
                    if (row >= M_ROWS) continue;
                    int bb = row / SEQ_N;
                    int n = row - bb * SEQ_N;
                    float v0 = c[mt][nt][hr * 2 + 0];
                    float v1 = c[mt][nt][hr * 2 + 1];
                    if (sidx < 2 && n >= 1) {
                        int t = n - 1;
                        float ang = (float)(t & 31) * f0 + (float)(t >> 5) * f1;
                        float sn, cs;
                        sincosf(ang, &sn, &cs);
                        float a0 = v0, b0 = v1;
                        v0 = a0 * cs - b0 * sn;
                        v1 = a0 * sn + b0 * cs;
                    }
                    int bh = bb * NHEAD + hh;
                    if (sidx == 0) {
                        size_t pos = (size_t)bh * QBUF_BH
                            + (size_t)((n >> 4) * 4 + (e0 >> 4)) * 128
                            + ((n & 7) * 4 + l3) * 4 + ((n >> 3) & 1) + 2 * (nt & 1);
                        g_Q[pos] = f2h2(v0 * qscale, v1 * qscale);
                    } else if (sidx == 1) {
                        size_t pos = (size_t)bh * KVBUF_BH + (size_t)(n >> 6) * 2048
                            + (size_t)(((n & 63) >> 3) * 2 + (nt >> 2)) * 128
                            + ((n & 7) * 4 + l3) * 4 + ((nt >> 1) & 1) * 2 + (nt & 1);
                        g_K[pos] = f2h2(v0, v1);
                    } else {
                        size_t p0 = (size_t)bh * KVBUF_BH + (size_t)(n >> 6) * 2048
                            + (size_t)((e0 >> 3) * 2 + ((n >> 5) & 1)) * 128
                            + ((e0 & 7) * 4 + ((n & 7) >> 1)) * 4
                            + (((n >> 4) & 1) * 2) + ((n >> 3) & 1);
                        __half* hp = (__half*)g_V;
                        hp[p0 * 2 + (n & 1)] = __float2half(v0);
                        hp[(p0 + 16) * 2 + (n & 1)] = __float2half(v1);
                    }
                }
        }
    } else {
#pragma unroll
        for (int nt = 0; nt < 8; nt++) {
            int col = n0 + wn * 64 + nt * 8 + 2 * l3;
            float b0v = bias[col], b1v = bias[col + 1];
#pragma unroll
            for (int mt = 0; mt < 2; mt++)
#pragma unroll
                for (int hr = 0; hr < 2; hr++) {
                    int row = m0 + wm * 32 + mt * 16 + s7 + hr * 8;
                    if (row >= M_ROWS) continue;
                    *(float2*)&out[(size_t)row * DMODEL + col] =
                        make_float2(c[mt][nt][hr * 2 + 0] + b0v,
                                    c[mt][nt][hr * 2 + 1] + b1v);
                }
        }
    }
}

// =================================================================
// Flash attention, fp16 TC, max-free exp2 softmax, paired K/V
// LDS.128 layouts (R13). l row-sums moved OFF the tensor pipe:
// accumulated as float2 on the FMA pipe, reduced once at the end.
// =================================================================
#define ATTN_SMEM_BYTES (3 * 4096 * 4)

__global__ __launch_bounds__(256, 2) void attn_tc()
{
    extern __shared__ uint32_t dsm[];

    const int tid = threadIdx.x;
    const int lane = tid & 31;
    const int w = tid >> 5;
    const int bx = blockIdx.x;
    const int q0 = bx * 128;
    const int bh = blockIdx.y;

    const uint32_t* Kg = g_K + (size_t)bh * KVBUF_BH;
    const uint32_t* Vg = g_V + (size_t)bh * KVBUF_BH;
    const uint32_t smBase = (uint32_t)__cvta_generic_to_shared(dsm);

    auto issue_kv = [&](int kt, int s) {
        const uint32_t buf = smBase + s * 4096 * 4;
        const uint32_t* ks = Kg + kt * 2048;
        const uint32_t* vs = Vg + kt * 2048;
#pragma unroll
        for (int it = 0; it < 2; it++) {
            int ch = tid + it * 256;
            cpa16u(buf + ch * 16, ks + ch * 4);
            cpa16u(buf + 8192 + ch * 16, vs + ch * 4);
        }
        CPA_COMMIT();
    };

    const int qg = bx * 8 + w;
    const bool act = (qg < 65);
    uint32_t qa[4][4];
    if (act) {
        const uint32_t* Qg = g_Q + (size_t)bh * QBUF_BH + (size_t)qg * 512;
#pragma unroll
        for (int kg = 0; kg < 4; kg++) {
            uint4 qv = *(const uint4*)&Qg[kg * 128 + lane * 4];
            qa[kg][0] = qv.x; qa[kg][1] = qv.y; qa[kg][2] = qv.z; qa[kg][3] = qv.w;
        }
    }

    float of[8][4];
#pragma unroll
    for (int i = 0; i < 8; i++)
#pragma unroll
        for (int j = 0; j < 4; j++) of[i][j] = 0.f;
    float2 la0 = make_float2(0.f, 0.f);   // row r0 partial sums
    float2 la1 = make_float2(0.f, 0.f);   // row r0+8 partial sums

    issue_kv(0, 0);
    issue_kv(1, 1);

    for (int kt = 0; kt < 17; kt++) {
        const int kv0 = kt * 64;
        if (kt + 1 < 17) CPA_WAIT1(); else CPA_WAIT0();
        __syncthreads();
        if (kt + 2 < 17) issue_kv(kt + 2, (kt + 2) % 3);

        if (act) {
            const uint32_t* Ks = dsm + (kt % 3) * 4096;
            const uint32_t* Vs = Ks + 2048;

            // ---- S = Q K^T ----
            float s[8][4];
#pragma unroll
            for (int i = 0; i < 8; i++)
#pragma unroll
                for (int j = 0; j < 4; j++) s[i][j] = 0.f;
#pragma unroll
            for (int nt = 0; nt < 8; nt++) {
                uint4 u = *(const uint4*)&Ks[nt * 256 + lane * 4];
                uint4 v = *(const uint4*)&Ks[nt * 256 + 128 + lane * 4];
                mma16(s[nt], qa[0], u.x, u.y);
                mma16(s[nt], qa[1], u.z, u.w);
                mma16(s[nt], qa[2], v.x, v.y);
                mma16(s[nt], qa[3], v.z, v.w);
            }

            if (kt == 16) {
#pragma unroll
                for (int nt = 0; nt < 8; nt++) {
                    int col = kv0 + nt * 8 + 2 * (lane & 3);
                    if (col >= SEQ_N)     { s[nt][0] = -1e30f; s[nt][2] = -1e30f; }
                    if (col + 1 >= SEQ_N) { s[nt][1] = -1e30f; s[nt][3] = -1e30f; }
                }
            }

            // ---- P = exp2(S) in fp16 A-frag form ----
            uint32_t pa[4][4];
#pragma unroll
            for (int kg = 0; kg < 4; kg++) {
                pa[kg][0] = p_exp2(s[2 * kg][0],     s[2 * kg][1]);
                pa[kg][1] = p_exp2(s[2 * kg][2],     s[2 * kg][3]);
                pa[kg][2] = p_exp2(s[2 * kg + 1][0], s[2 * kg + 1][1]);
                pa[kg][3] = p_exp2(s[2 * kg + 1][2], s[2 * kg + 1][3]);
            }

            // ---- l accumulation on the FMA pipe (tensor pipe is the binder) ----
#pragma unroll
            for (int kg = 0; kg < 4; kg++) {
                float2 u0 = h2f2(pa[kg][0]);
                float2 u2 = h2f2(pa[kg][2]);
                la0.x += u0.x + u2.x;
                la0.y += u0.y + u2.y;
                float2 u1 = h2f2(pa[kg][1]);
                float2 u3 = h2f2(pa[kg][3]);
                la1.x += u1.x + u3.x;
                la1.y += u1.y + u3.y;
            }

            // ---- O += P V ----
#pragma unroll
            for (int ne = 0; ne < 8; ne++) {
                uint4 u = *(const uint4*)&Vs[ne * 256 + lane * 4];
                uint4 v = *(const uint4*)&Vs[ne * 256 + 128 + lane * 4];
                mma16(of[ne], pa[0], u.x, u.y);
                mma16(of[ne], pa[1], u.z, u.w);
                mma16(of[ne], pa[2], v.x, v.y);
                mma16(of[ne], pa[3], v.z, v.w);
            }
        }
    }

    // ---- final l reduction (quad shuffles) + normalize + write ctx ----
    if (act) {
        float l0 = la0.x + la0.y;
        float l1 = la1.x + la1.y;
        l0 += __shfl_xor_sync(0xffffffffu, l0, 1);
        l0 += __shfl_xor_sync(0xffffffffu, l0, 2);
        l1 += __shfl_xor_sync(0xffffffffu, l1, 1);
        l1 += __shfl_xor_sync(0xffffffffu, l1, 2);
        float inv0 = 1.f / l0, inv1 = 1.f / l1;
        const int hh = bh % NHEAD;
        const int bb = bh / NHEAD;
        const int l3 = lane & 3;
        const int qr0 = q0 + w * 16 + (lane >> 2);
        const int qr1 = qr0 + 8;
#pragma unroll
        for (int ne = 0; ne < 8; ne++) {
            int d = hh * 64 + ne * 8 + 2 * l3;
            int kg = d >> 4;
            if (qr0 < SEQ_N) {
                int m = bb * SEQ_N + qr0;
                size_t pos = ((size_t)(m >> 4) * KG + kg) * 128
                    + ((m & 7) * 4 + l3) * 4 + ((m >> 3) & 1) + 2 * (ne & 1);
                g_ctxp[pos] = f2h2(of[ne][0] * inv0, of[ne][1] * inv0);
            }
            if (qr1 < SEQ_N) {
                int m = bb * SEQ_N + qr1;
                size_t pos = ((size_t)(m >> 4) * KG + kg) * 128
                    + ((m & 7) * 4 + l3) * 4 + ((m >> 3) & 1) + 2 * (ne & 1);
                g_ctxp[pos] = f2h2(of[ne][2] * inv1, of[ne][3] * inv1);
            }
        }
    }
}

// =================================================================
extern "C" void kernel_launch(void* const* d_in, const int* in_sizes, int n_in,
                              void* d_out, int out_size)
{
    const float* x     = (const float*)d_in[0];
    const float* Wqkv  = (const float*)d_in[1];
    const float* Wproj = (const float*)d_in[2];
    const float* bproj = (const float*)d_in[3];
    const float* freqs = (const float*)d_in[4];
    float* out = (float*)d_out;

    uint32_t* xt;  cudaGetSymbolAddress((void**)&xt, g_xt);
    uint32_t* wq;  cudaGetSymbolAddress((void**)&wq, g_wq);
    uint32_t* wp;  cudaGetSymbolAddress((void**)&wp, g_wp);

    cudaFuncSetAttribute(gemm_tc<0>, cudaFuncAttributeMaxDynamicSharedMemorySize,
                         GEMM_SMEM_BYTES);
    cudaFuncSetAttribute(gemm_tc<1>, cudaFuncAttributeMaxDynamicSharedMemorySize,
                         GEMM_SMEM_BYTES);
    cudaFuncSetAttribute(attn_tc, cudaFuncAttributeMaxDynamicSharedMemorySize,
                         ATTN_SMEM_BYTES);

    // 0) prepass
    {
        int na = M_ROWS * 384;
        pack_a<<<(na + 255) / 256, 256>>>(x, xt, na);
        int nq = 2304 * 384;
        pack_w<<<(nq + 255) / 256, 256>>>(Wqkv, wq, nq);
        int np = 768 * 384;
        pack_w<<<(np + 255) / 256, 256>>>(Wproj, wp, np);
        zero_pad<<<(NBH * 2048 + 255) / 256, 256>>>();
    }
    // 1) QKV GEMM + fused RoPE -> packed Q/K/V
    {
        dim3 grid((M_ROWS + 127) / 128, (3 * DMODEL) / 128);
        gemm_tc<0><<<grid, 256, GEMM_SMEM_BYTES>>>(nullptr, nullptr, freqs);
    }
    // 2) attention -> packed ctx
    {
        dim3 grid((SEQ_N + 127) / 128, NBH);
        attn_tc<<<grid, 256, ATTN_SMEM_BYTES>>>();
    }
    // 3) proj GEMM + bias -> out
    {
        dim3 grid((M_ROWS + 127) / 128, DMODEL / 128);
        gemm_tc<1><<<grid, 256, GEMM_SMEM_BYTES>>>(out, bproj, nullptr);
    }
}

// round 17
// speedup vs baseline: 1.0307x; 1.0251x over previous
#include <cuda_runtime.h>
#include <cuda_fp16.h>
#include <cstdint>

#define NUM_B 16
#define SEQ_N 1025
#define NHEAD 12
#define HDIM  64
#define DMODEL 768
#define M_ROWS 16400
#define NBH (NUM_B * NHEAD)       // 192

// ---- packed geometry (fp16) ----
#define KG 48                     // 768/16
#define KGP 24                    // 768/32 (kg-pairs)
#define A_MG 1025                 // 16400/16
#define APK_SZ (A_MG * KG * 128)
#define WQ_NG 288                 // 2304/8
#define WP_NG 96
#define QBUF_BH (65 * 4 * 128)    // 33280 u32 per bh
#define KVBUF_BH (17 * 2048)      // 34816 u32 per bh
#define LOG2E 1.44269504088896340736f

// ---------------- scratch (fp16 bit patterns, packed) ----------------
__device__ uint32_t g_xt[APK_SZ];
__device__ uint32_t g_ctxp[APK_SZ];
__device__ uint32_t g_wq[WQ_NG * KGP * 128];
__device__ uint32_t g_wp[WP_NG * KGP * 128];
__device__ uint32_t g_Q[NBH * QBUF_BH];
__device__ uint32_t g_K[NBH * KVBUF_BH];
__device__ uint32_t g_V[NBH * KVBUF_BH];

__device__ __forceinline__ uint32_t f2h2(float lo, float hi) {
    __half2 h = __floats2half2_rn(lo, hi);
    return *(uint32_t*)&h;
}
__device__ __forceinline__ uint32_t p_exp2(float lo, float hi) {
    uint32_t r;
    asm("{\n\t.reg .b32 t;\n\t"
        "cvt.rn.f16x2.f32 t, %2, %1;\n\t"
        "ex2.approx.f16x2 %0, t;\n\t}"
        : "=r"(r) : "f"(lo), "f"(hi));
    return r;
}
__device__ __forceinline__ void mma16(float* c, const uint32_t* a, uint32_t b0, uint32_t b1) {
    asm volatile(
        "mma.sync.aligned.m16n8k16.row.col.f32.f16.f16.f32 "
        "{%0,%1,%2,%3}, {%4,%5,%6,%7}, {%8,%9}, {%0,%1,%2,%3};\n"
        : "+f"(c[0]), "+f"(c[1]), "+f"(c[2]), "+f"(c[3])
        : "r"(a[0]), "r"(a[1]), "r"(a[2]), "r"(a[3]), "r"(b0), "r"(b1));
}
__device__ __forceinline__ void cpa16(uint32_t dst, const void* src, int sz) {
    asm volatile("cp.async.cg.shared.global [%0], [%1], 16, %2;\n"
                 :: "r"(dst), "l"(src), "r"(sz));
}
__device__ __forceinline__ void cpa16u(uint32_t dst, const void* src) {
    asm volatile("cp.async.cg.shared.global [%0], [%1], 16;\n"
                 :: "r"(dst), "l"(src));
}
#define CPA_COMMIT() asm volatile("cp.async.commit_group;\n")
#define CPA_WAIT0()  asm volatile("cp.async.wait_group 0;\n")
#define CPA_WAIT1()  asm volatile("cp.async.wait_group 1;\n")

// ---------------- fused prepass: pack x, Wqkv, Wproj + zero K/V pad ----------------
#define N_A  (M_ROWS * 384)          // 6,297,600
#define N_WQ (2304 * 384)            // 884,736
#define N_WP (768 * 384)             // 294,912
#define N_Z  (NBH * 2048)            // 393,216
#define N_TOT (N_A + N_WQ + N_WP + N_Z)

__global__ void prep_all(const float* __restrict__ x,
                         const float* __restrict__ Wqkv,
                         const float* __restrict__ Wproj)
{
    int id = blockIdx.x * 256 + threadIdx.x;
    if (id < N_A) {
        // A-frag pack: x -> g_xt
        int m = id / 384;
        int c = id - m * 384;
        float2 v = *(const float2*)&x[(size_t)m * DMODEL + c * 2];
        g_xt[((size_t)(m >> 4) * KG + (c >> 3)) * 128
             + ((m & 7) * 4 + (c & 3)) * 4 + ((m >> 3) & 1) + 2 * ((c >> 2) & 1)]
            = f2h2(v.x, v.y);
        return;
    }
    id -= N_A;
    if (id < N_WQ) {
        // B-frag (kg-pair) pack: Wqkv -> g_wq
        int nn = id / 384;
        int c = id - nn * 384;
        float2 v = *(const float2*)&Wqkv[(size_t)nn * DMODEL + c * 2];
        g_wq[((size_t)(nn >> 3) * KGP + (c >> 4)) * 128
             + ((nn & 7) * 4 + (c & 3)) * 4 + ((c >> 3) & 1) * 2 + ((c >> 2) & 1)]
            = f2h2(v.x, v.y);
        return;
    }
    id -= N_WQ;
    if (id < N_WP) {
        int nn = id / 384;
        int c = id - nn * 384;
        float2 v = *(const float2*)&Wproj[(size_t)nn * DMODEL + c * 2];
        g_wp[((size_t)(nn >> 3) * KGP + (c >> 4)) * 128
             + ((nn & 7) * 4 + (c & 3)) * 4 + ((c >> 3) & 1) * 2 + ((c >> 2) & 1)]
            = f2h2(v.x, v.y);
        return;
    }
    id -= N_WP;
    if (id < N_Z) {
        int bh = id >> 11;
        int i = id & 2047;
        g_K[(size_t)bh * KVBUF_BH + 16 * 2048 + i] = 0;
        g_V[(size_t)bh * KVBUF_BH + 16 * 2048 + i] = 0;
    }
}

// =================================================================
// TN GEMM, fp16 TC (m16n8k16), 3-stage cp.async, packed frags.
// Block 128x128, 256 thr, 8 warps (4m x 2n), warp 32x64, k-step 32.
// (R13-identical — proven best)
// =================================================================
#define GEMM_SMEM_BYTES (3 * 4096 * 4)

template<int MODE>
__global__ __launch_bounds__(256, 2) void gemm_tc(
    float* __restrict__ out, const float* __restrict__ bias,
    const float* __restrict__ freqs)
{
    extern __shared__ uint32_t gsm[];

    const int tid = threadIdx.x;
    const int lane = tid & 31;
    const int wid = tid >> 5;
    const int wm = wid & 3;
    const int wn = wid >> 2;
    const int m0 = blockIdx.x * 128;
    const int n0 = blockIdx.y * 128;

    const uint32_t* Ag = (MODE == 1) ? g_ctxp : g_xt;
    const uint32_t* Bg = (MODE == 1) ? g_wp : g_wq;

    const uint32_t smAddr = (uint32_t)__cvta_generic_to_shared(gsm);

    float c[2][8][4];
#pragma unroll
    for (int i = 0; i < 2; i++)
#pragma unroll
        for (int j = 0; j < 8; j++)
#pragma unroll
            for (int r = 0; r < 4; r++) c[i][j][r] = 0.f;

    const int s7 = lane >> 2;
    const int l3 = lane & 3;
    const int mg0 = m0 >> 4;
    const int ng0 = n0 >> 3;

    auto stage_ld = [&](int k0, int s) {
        const int kg0 = k0 >> 4;
        const int kp0 = k0 >> 5;
#pragma unroll
        for (int it = 0; it < 2; it++) {
            int ch = tid + it * 256;
            int blk = ch >> 5;
            int inner = (ch & 31) * 4;
            int mg = mg0 + (blk >> 1);
            int sz = (mg < A_MG) ? 16 : 0;
            cpa16(smAddr + (s * 4096 + blk * 128 + inner) * 4,
                  &Ag[((size_t)mg * KG + kg0 + (blk & 1)) * 128 + inner], sz);
        }
#pragma unroll
        for (int it = 0; it < 2; it++) {
            int ch = tid + it * 256;
            int nb = ch >> 5;
            int inner = (ch & 31) * 4;
            cpa16u(smAddr + (s * 4096 + 2048 + nb * 128 + inner) * 4,
                   &Bg[((size_t)(ng0 + nb) * KGP + kp0) * 128 + inner]);
        }
        CPA_COMMIT();
    };

    stage_ld(0, 0);
    stage_ld(32, 1);

    for (int k0 = 0, it = 0; k0 < DMODEL; k0 += 32, it++) {
        if (k0 + 32 < DMODEL) CPA_WAIT1(); else CPA_WAIT0();
        __syncthreads();
        if (k0 + 64 < DMODEL) stage_ld(k0 + 64, (it + 2) % 3);

        const uint32_t* Ab = gsm + (it % 3) * 4096;
        const uint32_t* Bb = Ab + 2048;

        uint4 bv[8];
#pragma unroll
        for (int nt = 0; nt < 8; nt++)
            bv[nt] = *(const uint4*)&Bb[((wn * 8 + nt) << 7) + lane * 4];

#pragma unroll
        for (int kgi = 0; kgi < 2; kgi++) {
            uint32_t a[2][4];
#pragma unroll
            for (int mt = 0; mt < 2; mt++) {
                uint4 av = *(const uint4*)&Ab[(((wm * 2 + mt) * 2 + kgi) << 7) + lane * 4];
                a[mt][0] = av.x; a[mt][1] = av.y; a[mt][2] = av.z; a[mt][3] = av.w;
            }
#pragma unroll
            for (int mt = 0; mt < 2; mt++)
#pragma unroll
                for (int nt = 0; nt < 8; nt++) {
                    if (kgi == 0) mma16(c[mt][nt], a[mt], bv[nt].x, bv[nt].y);
                    else          mma16(c[mt][nt], a[mt], bv[nt].z, bv[nt].w);
                }
        }
    }

    // -------- epilogue (R13-identical) --------
    if (MODE == 0) {
        const int sidx = n0 / DMODEL;
        const int hh = ((n0 % DMODEL) >> 6) + wn;
        const float qscale = 0.125f * LOG2E;
#pragma unroll
        for (int nt = 0; nt < 8; nt++) {
            int e0 = nt * 8 + 2 * l3;
            float f0 = 0.f, f1 = 0.f;
            if (sidx < 2) {
                int fi = hh * 32 + (e0 >> 1);
                f0 = freqs[fi];
                f1 = freqs[384 + fi];
            }
#pragma unroll
            for (int mt = 0; mt < 2; mt++)
#pragma unroll
                for (int hr = 0; hr < 2; hr++) {
                    int row = m0 + wm * 32 + mt * 16 + s7 + hr * 8;
                    if (row >= M_ROWS) continue;
                    int bb = row / SEQ_N;
                    int n = row - bb * SEQ_N;
                    float v0 = c[mt][nt][hr * 2 + 0];
                    float v1 = c[mt][nt][hr * 2 + 1];
                    if (sidx < 2 && n >= 1) {
                        int t = n - 1;
                        float ang = (float)(t & 31) * f0 + (float)(t >> 5) * f1;
                        float sn, cs;
                        sincosf(ang, &sn, &cs);
                        float a0 = v0, b0 = v1;
                        v0 = a0 * cs - b0 * sn;
                        v1 = a0 * sn + b0 * cs;
                    }
                    int bh = bb * NHEAD + hh;
                    if (sidx == 0) {
                        size_t pos = (size_t)bh * QBUF_BH
                            + (size_t)((n >> 4) * 4 + (e0 >> 4)) * 128
                            + ((n & 7) * 4 + l3) * 4 + ((n >> 3) & 1) + 2 * (nt & 1);
                        g_Q[pos] = f2h2(v0 * qscale, v1 * qscale);
                    } else if (sidx == 1) {
                        size_t pos = (size_t)bh * KVBUF_BH + (size_t)(n >> 6) * 2048
                            + (size_t)(((n & 63) >> 3) * 2 + (nt >> 2)) * 128
                            + ((n & 7) * 4 + l3) * 4 + ((nt >> 1) & 1) * 2 + (nt & 1);
                        g_K[pos] = f2h2(v0, v1);
                    } else {
                        size_t p0 = (size_t)bh * KVBUF_BH + (size_t)(n >> 6) * 2048
                            + (size_t)((e0 >> 3) * 2 + ((n >> 5) & 1)) * 128
                            + ((e0 & 7) * 4 + ((n & 7) >> 1)) * 4
                            + (((n >> 4) & 1) * 2) + ((n >> 3) & 1);
                        __half* hp = (__half*)g_V;
                        hp[p0 * 2 + (n & 1)] = __float2half(v0);
                        hp[(p0 + 16) * 2 + (n & 1)] = __float2half(v1);
                    }
                }
        }
    } else {
#pragma unroll
        for (int nt = 0; nt < 8; nt++) {
            int col = n0 + wn * 64 + nt * 8 + 2 * l3;
            float b0v = bias[col], b1v = bias[col + 1];
#pragma unroll
            for (int mt = 0; mt < 2; mt++)
#pragma unroll
                for (int hr = 0; hr < 2; hr++) {
                    int row = m0 + wm * 32 + mt * 16 + s7 + hr * 8;
                    if (row >= M_ROWS) continue;
                    *(float2*)&out[(size_t)row * DMODEL + col] =
                        make_float2(c[mt][nt][hr * 2 + 0] + b0v,
                                    c[mt][nt][hr * 2 + 1] + b1v);
                }
        }
    }
}

// =================================================================
// Flash attention (R13-identical — proven best): fp16 TC, max-free
// exp2 softmax, paired K/V LDS.128 layouts, l via ones-MMA,
// idle-warp skip, 3-stage cp.async KV.
// =================================================================
#define ATTN_SMEM_BYTES (3 * 4096 * 4)

__global__ __launch_bounds__(256, 2) void attn_tc()
{
    extern __shared__ uint32_t dsm[];

    const int tid = threadIdx.x;
    const int lane = tid & 31;
    const int w = tid >> 5;
    const int bx = blockIdx.x;
    const int q0 = bx * 128;
    const int bh = blockIdx.y;

    const uint32_t* Kg = g_K + (size_t)bh * KVBUF_BH;
    const uint32_t* Vg = g_V + (size_t)bh * KVBUF_BH;
    const uint32_t smBase = (uint32_t)__cvta_generic_to_shared(dsm);

    auto issue_kv = [&](int kt, int s) {
        const uint32_t buf = smBase + s * 4096 * 4;
        const uint32_t* ks = Kg + kt * 2048;
        const uint32_t* vs = Vg + kt * 2048;
#pragma unroll
        for (int it = 0; it < 2; it++) {
            int ch = tid + it * 256;
            cpa16u(buf + ch * 16, ks + ch * 4);
            cpa16u(buf + 8192 + ch * 16, vs + ch * 4);
        }
        CPA_COMMIT();
    };

    const int qg = bx * 8 + w;
    const bool act = (qg < 65);
    uint32_t qa[4][4];
    if (act) {
        const uint32_t* Qg = g_Q + (size_t)bh * QBUF_BH + (size_t)qg * 512;
#pragma unroll
        for (int kg = 0; kg < 4; kg++) {
            uint4 qv = *(const uint4*)&Qg[kg * 128 + lane * 4];
            qa[kg][0] = qv.x; qa[kg][1] = qv.y; qa[kg][2] = qv.z; qa[kg][3] = qv.w;
        }
    }

    float of[8][4];
#pragma unroll
    for (int i = 0; i < 8; i++)
#pragma unroll
        for (int j = 0; j < 4; j++) of[i][j] = 0.f;
    float lc[4] = {0.f, 0.f, 0.f, 0.f};

    issue_kv(0, 0);
    issue_kv(1, 1);

    for (int kt = 0; kt < 17; kt++) {
        const int kv0 = kt * 64;
        if (kt + 1 < 17) CPA_WAIT1(); else CPA_WAIT0();
        __syncthreads();
        if (kt + 2 < 17) issue_kv(kt + 2, (kt + 2) % 3);

        if (act) {
            const uint32_t* Ks = dsm + (kt % 3) * 4096;
            const uint32_t* Vs = Ks + 2048;

            // ---- S = Q K^T (paired: 2 LDS.128 per key-octet) ----
            float s[8][4];
#pragma unroll
            for (int i = 0; i < 8; i++)
#pragma unroll
                for (int j = 0; j < 4; j++) s[i][j] = 0.f;
#pragma unroll
            for (int nt = 0; nt < 8; nt++) {
                uint4 u = *(const uint4*)&Ks[nt * 256 + lane * 4];
                uint4 v = *(const uint4*)&Ks[nt * 256 + 128 + lane * 4];
                mma16(s[nt], qa[0], u.x, u.y);
                mma16(s[nt], qa[1], u.z, u.w);
                mma16(s[nt], qa[2], v.x, v.y);
                mma16(s[nt], qa[3], v.z, v.w);
            }

            if (kt == 16) {
#pragma unroll
                for (int nt = 0; nt < 8; nt++) {
                    int col = kv0 + nt * 8 + 2 * (lane & 3);
                    if (col >= SEQ_N)     { s[nt][0] = -1e30f; s[nt][2] = -1e30f; }
                    if (col + 1 >= SEQ_N) { s[nt][1] = -1e30f; s[nt][3] = -1e30f; }
                }
            }

            // ---- P = exp2(S) in fp16 A-frag form ----
            uint32_t pa[4][4];
#pragma unroll
            for (int kg = 0; kg < 4; kg++) {
                pa[kg][0] = p_exp2(s[2 * kg][0],     s[2 * kg][1]);
                pa[kg][1] = p_exp2(s[2 * kg][2],     s[2 * kg][3]);
                pa[kg][2] = p_exp2(s[2 * kg + 1][0], s[2 * kg + 1][1]);
                pa[kg][3] = p_exp2(s[2 * kg + 1][2], s[2 * kg + 1][3]);
            }

            // ---- l += P @ ones ----
#pragma unroll
            for (int kg = 0; kg < 4; kg++)
                mma16(lc, pa[kg], 0x3C003C00u, 0x3C003C00u);

            // ---- O += P V (paired: 2 LDS.128 per e-octet) ----
#pragma unroll
            for (int ne = 0; ne < 8; ne++) {
                uint4 u = *(const uint4*)&Vs[ne * 256 + lane * 4];
                uint4 v = *(const uint4*)&Vs[ne * 256 + 128 + lane * 4];
                mma16(of[ne], pa[0], u.x, u.y);
                mma16(of[ne], pa[1], u.z, u.w);
                mma16(of[ne], pa[2], v.x, v.y);
                mma16(of[ne], pa[3], v.z, v.w);
            }
        }
    }

    // ---- normalize + write ctx (packed A-frag, fp16 bits) ----
    if (act) {
        float inv0 = 1.f / lc[0], inv1 = 1.f / lc[2];
        const int hh = bh % NHEAD;
        const int bb = bh / NHEAD;
        const int l3 = lane & 3;
        const int qr0 = q0 + w * 16 + (lane >> 2);
        const int qr1 = qr0 + 8;
#pragma unroll
        for (int ne = 0; ne < 8; ne++) {
            int d = hh * 64 + ne * 8 + 2 * l3;
            int kg = d >> 4;
            if (qr0 < SEQ_N) {
                int m = bb * SEQ_N + qr0;
                size_t pos = ((size_t)(m >> 4) * KG + kg) * 128
                    + ((m & 7) * 4 + l3) * 4 + ((m >> 3) & 1) + 2 * (ne & 1);
                g_ctxp[pos] = f2h2(of[ne][0] * inv0, of[ne][1] * inv0);
            }
            if (qr1 < SEQ_N) {
                int m = bb * SEQ_N + qr1;
                size_t pos = ((size_t)(m >> 4) * KG + kg) * 128
                    + ((m & 7) * 4 + l3) * 4 + ((m >> 3) & 1) + 2 * (ne & 1);
                g_ctxp[pos] = f2h2(of[ne][2] * inv1, of[ne][3] * inv1);
            }
        }
    }
}

// =================================================================
extern "C" void kernel_launch(void* const* d_in, const int* in_sizes, int n_in,
                              void* d_out, int out_size)
{
    const float* x     = (const float*)d_in[0];
    const float* Wqkv  = (const float*)d_in[1];
    const float* Wproj = (const float*)d_in[2];
    const float* bproj = (const float*)d_in[3];
    const float* freqs = (const float*)d_in[4];
    float* out = (float*)d_out;

    cudaFuncSetAttribute(gemm_tc<0>, cudaFuncAttributeMaxDynamicSharedMemorySize,
                         GEMM_SMEM_BYTES);
    cudaFuncSetAttribute(gemm_tc<1>, cudaFuncAttributeMaxDynamicSharedMemorySize,
                         GEMM_SMEM_BYTES);
    cudaFuncSetAttribute(attn_tc, cudaFuncAttributeMaxDynamicSharedMemorySize,
                         ATTN_SMEM_BYTES);

    // 0) fused prepass: pack x/Wqkv/Wproj + zero K/V pad (one launch)
    prep_all<<<(N_TOT + 255) / 256, 256>>>(x, Wqkv, Wproj);

    // 1) QKV GEMM + fused RoPE -> packed Q/K/V
    {
        dim3 grid((M_ROWS + 127) / 128, (3 * DMODEL) / 128);
        gemm_tc<0><<<grid, 256, GEMM_SMEM_BYTES>>>(nullptr, nullptr, freqs);
    }
    // 2) attention -> packed ctx
    {
        dim3 grid((SEQ_N + 127) / 128, NBH);
        attn_tc<<<grid, 256, ATTN_SMEM_BYTES>>>();
    }
    // 3) proj GEMM + bias -> out
    {
        dim3 grid((M_ROWS + 127) / 128, DMODEL / 128);
        gemm_tc<1><<<grid, 256, GEMM_SMEM_BYTES>>>(out, bproj, nullptr);
    }
}